// round 15
// baseline (speedup 1.0000x reference)
#include <cuda_runtime.h>
#include <cuda_bf16.h>
#include <cstdint>
#include <cstddef>

// Problem constants
#define HWC   65536          // H*W = 256*256
#define CCH   256            // channels
#define NBAT  4
#define NHEAD 8
#define HD    32
#define NGRP  32
#define CPG   8              // channels per group

// ===========================================================================
// Helpers
// ===========================================================================
__device__ __forceinline__ uint32_t smem_u32(const void* p) {
    uint32_t a;
    asm("{ .reg .u64 t; cvta.to.shared.u64 t, %1; cvt.u32.u64 %0, t; }"
        : "=r"(a) : "l"(p));
    return a;
}
__device__ __forceinline__ void ldsm_x4(uint32_t* r, uint32_t addr) {
    asm volatile("ldmatrix.sync.aligned.m8n8.x4.shared.b16 {%0,%1,%2,%3}, [%4];"
        : "=r"(r[0]), "=r"(r[1]), "=r"(r[2]), "=r"(r[3]) : "r"(addr));
}
__device__ __forceinline__ void ldsm_x4t(uint32_t* r, uint32_t addr) {
    asm volatile("ldmatrix.sync.aligned.m8n8.x4.trans.shared.b16 {%0,%1,%2,%3}, [%4];"
        : "=r"(r[0]), "=r"(r[1]), "=r"(r[2]), "=r"(r[3]) : "r"(addr));
}
__device__ __forceinline__ void mma_bf16(float* c, const uint32_t* a, const uint32_t* b) {
    asm volatile("mma.sync.aligned.m16n8k16.row.col.f32.bf16.bf16.f32 "
        "{%0,%1,%2,%3}, {%4,%5,%6,%7}, {%8,%9}, {%0,%1,%2,%3};"
        : "+f"(c[0]), "+f"(c[1]), "+f"(c[2]), "+f"(c[3])
        : "r"(a[0]), "r"(a[1]), "r"(a[2]), "r"(a[3]), "r"(b[0]), "r"(b[1]));
}
__device__ __forceinline__ void cp16(uint32_t dst, const void* src) {
    asm volatile("cp.async.cg.shared.global [%0], [%1], 16;" :: "r"(dst), "l"(src));
}
#define CP_COMMIT() asm volatile("cp.async.commit_group;" ::: "memory")
#define CP_WAIT0()  asm volatile("cp.async.wait_group 0;" ::: "memory")
#define CP_WAIT1()  asm volatile("cp.async.wait_group 1;" ::: "memory")

__device__ __forceinline__ void store2(float* p, float x, float y) {
    *(float2*)p = make_float2(x, y);
}
__device__ __forceinline__ void store2(__nv_bfloat16* p, float x, float y) {
    *(__nv_bfloat162*)p = __floats2bfloat162_rn(x, y);
}
__device__ __forceinline__ uint32_t pack_bf2(float x, float y) {
    __nv_bfloat162 h = __floats2bfloat162_rn(x, y);
    return *reinterpret_cast<uint32_t*>(&h);
}
// spatial index n (= h*256+w) -> window-tiled index win*64 + tok
__device__ __forceinline__ int remap_win(int n) {
    return (((n >> 11) * 32 + ((n >> 3) & 31)) << 6) + (((n >> 8) & 7) << 3) + (n & 7);
}

// ---------------------------------------------------------------------------
// Scratch
// ---------------------------------------------------------------------------
__device__ float g_psum[NBAT * NGRP * 4 * 2];
__device__ __align__(16) __nv_bfloat16 g_wadjb[NBAT * 768 * 256];  // GN-folded QKV weights
__device__ __align__(16) __nv_bfloat16 g_owb[256 * 256];           // o_w bf16 [o][c]
__device__ float g_badj[NBAT * 768];
__device__ __align__(16) __nv_bfloat16 g_qbf[(size_t)NBAT * CCH * HWC];  // q in bf16
__device__ __align__(16) __nv_bfloat16 g_qkv[(size_t)NBAT * 768 * HWC];  // [b][768][win*64+tok]

// ---------------------------------------------------------------------------
// K1: GroupNorm partial sums + q -> bf16 conversion (512 blocks)
// ---------------------------------------------------------------------------
__global__ __launch_bounds__(256) void gn_part_kernel(const float* __restrict__ q,
                                                      __nv_bfloat16* __restrict__ qbf)
{
    const int bx = blockIdx.x;
    const int bg = bx >> 2, slice = bx & 3;
    const size_t off4 = (size_t)bg * (CPG * HWC / 4) + (size_t)slice * (CPG * HWC / 16);
    const float4* base = (const float4*)q + off4;
    __nv_bfloat16* qb = qbf + off4 * 4;
    float s = 0.f, s2 = 0.f;
#pragma unroll 4
    for (int i = threadIdx.x; i < CPG * HWC / 16; i += 256) {
        float4 v = base[i];
        s  += v.x + v.y + v.z + v.w;
        s2 += v.x*v.x + v.y*v.y + v.z*v.z + v.w*v.w;
        uint2 u;
        u.x = pack_bf2(v.x, v.y);
        u.y = pack_bf2(v.z, v.w);
        *(uint2*)(qb + (size_t)i * 4) = u;
    }
    __shared__ float rs[256], rs2[256];
    rs[threadIdx.x] = s; rs2[threadIdx.x] = s2;
    __syncthreads();
    for (int off = 128; off > 0; off >>= 1) {
        if (threadIdx.x < off) {
            rs [threadIdx.x] += rs [threadIdx.x + off];
            rs2[threadIdx.x] += rs2[threadIdx.x + off];
        }
        __syncthreads();
    }
    if (threadIdx.x == 0) {
        g_psum[bx * 2 + 0] = rs[0];
        g_psum[bx * 2 + 1] = rs2[0];
    }
}

// ---------------------------------------------------------------------------
// K2: finalize stats + fold GroupNorm into QKV weights (32^-0.5 into k)
// ---------------------------------------------------------------------------
__global__ __launch_bounds__(256) void prep_weights_kernel(
    const float* __restrict__ q_w, const float* __restrict__ q_b,
    const float* __restrict__ k_w, const float* __restrict__ k_b,
    const float* __restrict__ v_w, const float* __restrict__ v_b,
    const float* __restrict__ gn_w, const float* __restrict__ gn_b)
{
    int m = blockIdx.x;
    int b = blockIdx.y;
    int t = m >> 8, o = m & 255;
    const float* W; const float* Bv;
    if      (t == 0) { W = q_w; Bv = q_b; }
    else if (t == 1) { W = k_w; Bv = k_b; }
    else             { W = v_w; Bv = v_b; }
    const float KS = (t == 1) ? 0.17677669529663687f : 1.0f;

    int c = threadIdx.x;
    int g = c >> 3;
    const int bg = b * NGRP + g;
    float s  = g_psum[bg * 8 + 0] + g_psum[bg * 8 + 2] + g_psum[bg * 8 + 4] + g_psum[bg * 8 + 6];
    float s2 = g_psum[bg * 8 + 1] + g_psum[bg * 8 + 3] + g_psum[bg * 8 + 5] + g_psum[bg * 8 + 7];
    const float invN = 1.f / (float)(CPG * HWC);
    float mean = s * invN;
    float var  = s2 * invN - mean * mean;
    float rstd = rsqrtf(var + 1e-6f);

    float sc = rstd * gn_w[c];
    float sh = gn_b[c] - mean * sc;
    float wv = W[o * 256 + c];

    g_wadjb[((size_t)b * 768 + m) * 256 + c] = __float2bfloat16(wv * sc * KS);

    __shared__ float red[256];
    red[c] = wv * sh;
    __syncthreads();
    for (int off = 128; off > 0; off >>= 1) {
        if (c < off) red[c] += red[c + off];
        __syncthreads();
    }
    if (c == 0) g_badj[(size_t)b * 768 + m] = (Bv[o] + red[0]) * KS;
}

__global__ __launch_bounds__(256) void prep_ow_kernel(const float* __restrict__ ow)
{
    int o = blockIdx.x, c = threadIdx.x;
    g_owb[o * 256 + c] = __float2bfloat16(ow[o * 256 + c]);
}

// ---------------------------------------------------------------------------
// K3: QKV bf16 mma.sync GEMM (validated R13 pipeline), epilogue writes the
// window-tiled qkv layout (remap_win).
// ---------------------------------------------------------------------------
#define SM_X    0
#define SM_A    65536
#define SM_TOT  114688

__device__ __forceinline__ void stage_x(uint32_t sb, const __nv_bfloat16* Xb, int tid)
{
#pragma unroll 4
    for (int i = tid; i < 4096; i += 256) {
        int k = i >> 4, g = i & 15;
        cp16(sb + SM_X + k * 256 + ((g ^ (k & 7)) << 4),
             Xb + (size_t)k * HWC + g * 8);
    }
}
__device__ __forceinline__ void stage_aq(uint32_t sb, const __nv_bfloat16* Asrc,
                                         uint32_t buf, int tid)
{
#pragma unroll
    for (int i = tid; i < 1024; i += 256) {
        int m = i >> 3, ch = i & 7;
        cp16(sb + SM_A + buf * 16384 + m * 128 + ((ch ^ (m & 7)) << 4),
             Asrc + (size_t)m * 256 + ch * 8);
    }
}

__global__ __launch_bounds__(256, 2) void gemm_qkv_kernel(
    const __nv_bfloat16* __restrict__ Abf,
    const float* __restrict__ bias,
    const __nv_bfloat16* __restrict__ X,
    __nv_bfloat16* __restrict__ out)
{
    extern __shared__ char smem[];
    const uint32_t sb = smem_u32(smem);
    const int tid = threadIdx.x, wid = tid >> 5, lane = tid & 31;
    const int b = blockIdx.y;
    const int n0 = blockIdx.x * 128;
    const int MT = 6;

    const __nv_bfloat16* Ab = Abf + (size_t)b * 768 * 256;

    stage_x(sb, X + (size_t)b * CCH * HWC + n0, tid);
    stage_aq(sb, Ab, 0, tid);
    CP_COMMIT();
    stage_aq(sb, Ab + 64, 1, tid);
    CP_COMMIT();

    const int wm = (wid & 3) * 32;
    const int wn = (wid >> 2) * 64;
    const int arow = wm + (lane & 15);
    const int asel = lane >> 4;
    const int ar7  = arow & 7;
    const int gg = lane >> 3, ll = lane & 7;
    const int kbl = (gg & 1) * 8 + ll;
    const int br7 = kbl & 7;
    uint32_t bBase[4];
#pragma unroll
    for (int j = 0; j < 4; j++) {
        int cn = (wn >> 3) + j * 2 + (gg >> 1);
        bBase[j] = sb + SM_X + (uint32_t)kbl * 256 + (uint32_t)((cn ^ br7) << 4);
    }
    const int er = lane >> 2, ec = (lane & 3) * 2;

    int cur = 0;
    for (int mt = 0; mt < MT; mt++) {
        float c[2][8][4];
#pragma unroll
        for (int mi = 0; mi < 2; mi++)
#pragma unroll
            for (int ni = 0; ni < 8; ni++)
#pragma unroll
                for (int t = 0; t < 4; t++) c[mi][ni][t] = 0.f;

#pragma unroll
        for (int q = 0; q < 4; q++) {
            const int qi = mt * 4 + q;
            CP_WAIT1();
            __syncthreads();
            const int nqi = qi + 2;
            if (nqi < MT * 4) {
                const int nbuf = (cur == 0) ? 2 : cur - 1;
                stage_aq(sb, Ab + (size_t)(nqi >> 2) * 32768 + (nqi & 3) * 64,
                         (uint32_t)nbuf, tid);
            }
            CP_COMMIT();
            const uint32_t abuf = sb + SM_A + (uint32_t)cur * 16384;

#pragma unroll
            for (int ksl = 0; ksl < 4; ksl++) {
                uint32_t a0[4], a1[4];
                const uint32_t aoff = (uint32_t)(((ksl * 2 + asel) ^ ar7) << 4);
                ldsm_x4(a0, abuf + (uint32_t)arow * 128 + aoff);
                ldsm_x4(a1, abuf + (uint32_t)(arow + 16) * 128 + aoff);
                const uint32_t xoff = (uint32_t)(q * 16384 + ksl * 4096);
                uint32_t bf[8][2];
#pragma unroll
                for (int j = 0; j < 4; j++) {
                    uint32_t r[4];
                    ldsm_x4t(r, bBase[j] + xoff);
                    bf[2 * j][0] = r[0];     bf[2 * j][1] = r[1];
                    bf[2 * j + 1][0] = r[2]; bf[2 * j + 1][1] = r[3];
                }
#pragma unroll
                for (int ni = 0; ni < 8; ni++) {
                    mma_bf16(c[0][ni], a0, bf[ni]);
                    mma_bf16(c[1][ni], a1, bf[ni]);
                }
            }
            cur = (cur == 2) ? 0 : cur + 1;
        }

        // epilogue: bias + window-tiled remap store (bf16)
#pragma unroll
        for (int mi = 0; mi < 2; mi++) {
            const int m0g = mt * 128 + wm + mi * 16 + er;
            const float bv0 = bias[(size_t)b * 768 + m0g];
            const float bv1 = bias[(size_t)b * 768 + m0g + 8];
            __nv_bfloat16* ob = out + ((size_t)b * 768 + m0g) * HWC;
#pragma unroll
            for (int ni = 0; ni < 8; ni++) {
                const int nn = n0 + wn + ni * 8 + ec;
                const int pos = remap_win(nn);
                store2(ob + pos,           c[mi][ni][0] + bv0, c[mi][ni][1] + bv0);
                store2(ob + 8 * HWC + pos, c[mi][ni][2] + bv1, c[mi][ni][3] + bv1);
            }
        }
    }
}

// ---------------------------------------------------------------------------
// K4: fused windowed MHA + output projection + residual.
// One block per (window, batch): 512 threads = 16 warps.
//  Phase A (attention): warp w -> head w>>1, query-half w&1 (validated code).
//    Output written (normalized, bf16) to smem attnout[c=256][tok=64], B-swizzle.
//  Phase B (O-proj): out[256 oc][64 tok] = o_w @ attnout; o_w staged in 2x32KB
//    cp.async chunks; fused o_b bias + fp32 q residual + 2^-0.5 scale.
// smem: QKV 96KB + attnout 32KB + ow 64KB = 192KB -> 1 block/SM.
// ---------------------------------------------------------------------------
#define SMF_AT  98304
#define SMF_OW  131072
#define SMF_TOT 196608

__device__ __forceinline__ void stage_ow(uint32_t sb, const __nv_bfloat16* owb,
                                         int kc, uint32_t buf, int tid)
{
    const __nv_bfloat16* src = owb + kc * 64;
#pragma unroll
    for (int i = tid; i < 2048; i += 512) {
        int oc = i >> 3, ch = i & 7;
        cp16(sb + SMF_OW + buf * 32768 + oc * 128 + ((ch ^ (oc & 7)) << 4),
             src + (size_t)oc * 256 + ch * 8);
    }
}

__global__ __launch_bounds__(512) void attn_oproj_kernel(
    const __nv_bfloat16* __restrict__ qkv,
    const __nv_bfloat16* __restrict__ owb,
    const float* __restrict__ o_b,
    const float* __restrict__ qres,
    float* __restrict__ out)
{
    extern __shared__ char smem[];
    const uint32_t sb = smem_u32(smem);
    const int tid = threadIdx.x, wid = tid >> 5, lane = tid & 31;
    const int win = blockIdx.x, b = blockIdx.y;
    const int wy = win >> 5, wx = win & 31;
    const int h0 = wy * 8, w0 = wx * 8;

    // o_w chunks 0,1 in flight during attention
    stage_ow(sb, owb, 0, 0, tid); CP_COMMIT();
    stage_ow(sb, owb, 1, 1, tid); CP_COMMIT();

    // stage Q/K/V for all 8 heads (window-tiled source: fully contiguous rows)
    {
        const __nv_bfloat16* src = qkv + (size_t)b * 768 * HWC + (size_t)win * 64;
#pragma unroll
        for (int idx = tid; idx < 6144; idx += 512) {
            int chk = idx & 7, d = (idx >> 3) & 31, head = (idx >> 8) & 7, t = idx >> 11;
            int ch = t * 256 + head * 32 + d;
            uint4 v = *(const uint4*)(src + (size_t)ch * HWC + chk * 8);
            *(uint4*)(smem + head * 12288 + t * 4096 + d * 128 + ((chk ^ (d & 7)) << 4)) = v;
        }
    }
    __syncthreads();

    // ================= Phase A: attention =================
    const uint32_t Qs = sb + (wid >> 1) * 12288;
    const uint32_t Ks = Qs + 4096;
    const uint32_t Vs = Qs + 8192;
    const int mbase = (wid & 1) * 32;
    const int rlo = lane & 7, rsel = lane >> 4, csel = (lane >> 3) & 1;
    const int gg = lane >> 3, ll = lane & 7;

    {
        uint32_t qa[2][2][4];
#pragma unroll
        for (int mi = 0; mi < 2; mi++)
#pragma unroll
            for (int ks = 0; ks < 2; ks++) {
                int rd = ks * 16 + rsel * 8 + rlo;
                int chunk = (mbase >> 3) + mi * 2 + csel;
                ldsm_x4t(qa[mi][ks], Qs + rd * 128 + ((chunk ^ (rd & 7)) << 4));
            }

        float c[2][8][4];
#pragma unroll
        for (int mi = 0; mi < 2; mi++)
#pragma unroll
            for (int ni = 0; ni < 8; ni++)
#pragma unroll
                for (int t = 0; t < 4; t++) c[mi][ni][t] = 0.f;

#pragma unroll
        for (int ks = 0; ks < 2; ks++) {
            int rd = ks * 16 + rsel * 8 + rlo;
#pragma unroll
            for (int ng = 0; ng < 4; ng++) {
                int chunk = ng * 2 + csel;
                uint32_t r[4];
                ldsm_x4t(r, Ks + rd * 128 + ((chunk ^ (rd & 7)) << 4));
                uint32_t b0[2] = {r[0], r[2]}, b1[2] = {r[1], r[3]};
                mma_bf16(c[0][ng * 2],     qa[0][ks], b0);
                mma_bf16(c[0][ng * 2 + 1], qa[0][ks], b1);
                mma_bf16(c[1][ng * 2],     qa[1][ks], b0);
                mma_bf16(c[1][ng * 2 + 1], qa[1][ks], b1);
            }
        }

        float rs[2][2] = {{0.f, 0.f}, {0.f, 0.f}};
        uint32_t pa[2][4][4];
#pragma unroll
        for (int mi = 0; mi < 2; mi++)
#pragma unroll
            for (int ni = 0; ni < 8; ni++) {
                float e0 = __expf(c[mi][ni][0]);
                float e1 = __expf(c[mi][ni][1]);
                float e2 = __expf(c[mi][ni][2]);
                float e3 = __expf(c[mi][ni][3]);
                rs[mi][0] += e0 + e1;
                rs[mi][1] += e2 + e3;
                int ks = ni >> 1, half = ni & 1;
                pa[mi][ks][half * 2]     = pack_bf2(e0, e1);
                pa[mi][ks][half * 2 + 1] = pack_bf2(e2, e3);
            }
#pragma unroll
        for (int mi = 0; mi < 2; mi++)
#pragma unroll
            for (int j = 0; j < 2; j++) {
                rs[mi][j] += __shfl_xor_sync(0xffffffff, rs[mi][j], 1);
                rs[mi][j] += __shfl_xor_sync(0xffffffff, rs[mi][j], 2);
            }

        float o[2][4][4];
#pragma unroll
        for (int mi = 0; mi < 2; mi++)
#pragma unroll
            for (int nj = 0; nj < 4; nj++)
#pragma unroll
                for (int t = 0; t < 4; t++) o[mi][nj][t] = 0.f;

#pragma unroll
        for (int ks = 0; ks < 4; ks++) {
#pragma unroll
            for (int njg = 0; njg < 2; njg++) {
                int rd = njg * 16 + rsel * 8 + rlo;
                int chunk = ks * 2 + csel;
                uint32_t r[4];
                ldsm_x4(r, Vs + rd * 128 + ((chunk ^ (rd & 7)) << 4));
                uint32_t b0[2] = {r[0], r[1]}, b1[2] = {r[2], r[3]};
                mma_bf16(o[0][njg * 2],     pa[0][ks], b0);
                mma_bf16(o[0][njg * 2 + 1], pa[0][ks], b1);
                mma_bf16(o[1][njg * 2],     pa[1][ks], b0);
                mma_bf16(o[1][njg * 2 + 1], pa[1][ks], b1);
            }
        }

        // store normalized bf16 to attnout[c][tok] with B-operand swizzle
        const int headc = (wid >> 1) * 32;
#pragma unroll
        for (int mi = 0; mi < 2; mi++) {
            const float inv0 = 1.f / rs[mi][0];
            const float inv1 = 1.f / rs[mi][1];
            const int t0 = mbase + mi * 16 + (lane >> 2);
            const int t1 = t0 + 8;
#pragma unroll
            for (int nj = 0; nj < 4; nj++) {
                const int d0 = headc + nj * 8 + (lane & 3) * 2;
                const int d1 = d0 + 1;
                // addr(c,t) = c*128 + ((t>>3 ^ (c&7))<<4) + (t&7)*2
                *(__nv_bfloat16*)(smem + SMF_AT + d0 * 128 + (((t0 >> 3) ^ (d0 & 7)) << 4) + (t0 & 7) * 2)
                    = __float2bfloat16(o[mi][nj][0] * inv0);
                *(__nv_bfloat16*)(smem + SMF_AT + d1 * 128 + (((t0 >> 3) ^ (d1 & 7)) << 4) + (t0 & 7) * 2)
                    = __float2bfloat16(o[mi][nj][1] * inv0);
                *(__nv_bfloat16*)(smem + SMF_AT + d0 * 128 + (((t1 >> 3) ^ (d0 & 7)) << 4) + (t1 & 7) * 2)
                    = __float2bfloat16(o[mi][nj][2] * inv1);
                *(__nv_bfloat16*)(smem + SMF_AT + d1 * 128 + (((t1 >> 3) ^ (d1 & 7)) << 4) + (t1 & 7) * 2)
                    = __float2bfloat16(o[mi][nj][3] * inv1);
            }
        }
    }
    __syncthreads();
    CP_WAIT0();           // o_w chunks 0,1 resident
    __syncthreads();

    // ================= Phase B: O-projection =================
    const int arow = wid * 16 + (lane & 15);
    const int asel = lane >> 4;
    const int ar7  = arow & 7;
    const int kbl = (gg & 1) * 8 + ll;
    uint32_t bBase[4];
#pragma unroll
    for (int j = 0; j < 4; j++) {
        int cn = j * 2 + (gg >> 1);
        bBase[j] = sb + SMF_AT + (uint32_t)kbl * 128 + (uint32_t)((cn ^ (kbl & 7)) << 4);
    }

    float co[8][4];
#pragma unroll
    for (int ni = 0; ni < 8; ni++)
#pragma unroll
        for (int t = 0; t < 4; t++) co[ni][t] = 0.f;

#define OPROJ_CHUNK(KC, BUF) do {                                              \
    const uint32_t abufq = sb + SMF_OW + (uint32_t)(BUF) * 32768;              \
    _Pragma("unroll")                                                          \
    for (int ksl = 0; ksl < 4; ksl++) {                                        \
        uint32_t a[4];                                                         \
        ldsm_x4(a, abufq + (uint32_t)arow * 128                                \
                   + (uint32_t)(((ksl * 2 + asel) ^ ar7) << 4));               \
        const uint32_t xoff = (uint32_t)((KC) * 8192 + ksl * 2048);            \
        uint32_t bf[8][2];                                                     \
        _Pragma("unroll")                                                      \
        for (int j = 0; j < 4; j++) {                                          \
            uint32_t r[4];                                                     \
            ldsm_x4t(r, bBase[j] + xoff);                                      \
            bf[2 * j][0] = r[0];     bf[2 * j][1] = r[1];                      \
            bf[2 * j + 1][0] = r[2]; bf[2 * j + 1][1] = r[3];                  \
        }                                                                      \
        _Pragma("unroll")                                                      \
        for (int ni = 0; ni < 8; ni++) mma_bf16(co[ni], a, bf[ni]);            \
    }                                                                          \
} while (0)

    OPROJ_CHUNK(0, 0);
    __syncthreads();
    stage_ow(sb, owb, 2, 0, tid); CP_COMMIT();
    OPROJ_CHUNK(1, 1);
    __syncthreads();
    stage_ow(sb, owb, 3, 1, tid); CP_COMMIT();
    CP_WAIT1();
    __syncthreads();
    OPROJ_CHUNK(2, 0);
    CP_WAIT0();
    __syncthreads();
    OPROJ_CHUNK(3, 1);

    // epilogue: bias + fp32 residual + 2^-0.5, spatial layout
    {
        const int er = lane >> 2, ec = (lane & 3) * 2;
        const int oc0 = wid * 16 + er;
        const float bv0 = o_b[oc0], bv1 = o_b[oc0 + 8];
        const size_t base0 = ((size_t)b * 256 + oc0) * HWC;
        const float sc = 0.70710678118654752f;
#pragma unroll
        for (int ni = 0; ni < 8; ni++) {
            const int pos = (h0 + ni) * 256 + w0 + ec;
            float2 r0 = *(const float2*)(qres + base0 + pos);
            float2 r1 = *(const float2*)(qres + base0 + 8 * HWC + pos);
            store2(out + base0 + pos,
                   (co[ni][0] + bv0 + r0.x) * sc, (co[ni][1] + bv0 + r0.y) * sc);
            store2(out + base0 + 8 * HWC + pos,
                   (co[ni][2] + bv1 + r1.x) * sc, (co[ni][3] + bv1 + r1.y) * sc);
        }
    }
#undef OPROJ_CHUNK
}

// ---------------------------------------------------------------------------
// Launch
// ---------------------------------------------------------------------------
extern "C" void kernel_launch(void* const* d_in, const int* in_sizes, int n_in,
                              void* d_out, int out_size)
{
    const float* q    = (const float*)d_in[0];
    const float* gn_w = (const float*)d_in[1];
    const float* gn_b = (const float*)d_in[2];
    const float* q_w  = (const float*)d_in[3];
    const float* q_b  = (const float*)d_in[4];
    const float* k_w  = (const float*)d_in[5];
    const float* k_b  = (const float*)d_in[6];
    const float* v_w  = (const float*)d_in[7];
    const float* v_b  = (const float*)d_in[8];
    const float* o_w  = (const float*)d_in[9];
    const float* o_b  = (const float*)d_in[10];
    float* out = (float*)d_out;

    __nv_bfloat16 *p_wadjb, *p_owb, *p_qbf, *p_qkv;
    float *p_badj;
    cudaGetSymbolAddress((void**)&p_wadjb, g_wadjb);
    cudaGetSymbolAddress((void**)&p_owb,   g_owb);
    cudaGetSymbolAddress((void**)&p_badj,  g_badj);
    cudaGetSymbolAddress((void**)&p_qbf,   g_qbf);
    cudaGetSymbolAddress((void**)&p_qkv,   g_qkv);

    cudaFuncSetAttribute((const void*)gemm_qkv_kernel,
                         cudaFuncAttributeMaxDynamicSharedMemorySize, SM_TOT);
    cudaFuncSetAttribute((const void*)attn_oproj_kernel,
                         cudaFuncAttributeMaxDynamicSharedMemorySize, SMF_TOT);

    // 1. GroupNorm partial stats + q -> bf16
    gn_part_kernel<<<NBAT * NGRP * 4, 256>>>(q, p_qbf);

    // 2. Finalize stats + fold GN into QKV weights; o_w -> bf16
    prep_weights_kernel<<<dim3(768, NBAT), 256>>>(q_w, q_b, k_w, k_b, v_w, v_b, gn_w, gn_b);
    prep_ow_kernel<<<256, 256>>>(o_w);

    // 3. Fused (GN + QKV projection) -> window-tiled bf16 qkv
    gemm_qkv_kernel<<<dim3(512, NBAT), 256, SM_TOT>>>(p_wadjb, p_badj, p_qbf, p_qkv);

    // 4. Fused attention + O-proj + residual
    attn_oproj_kernel<<<dim3(1024, NBAT), 512, SMF_TOT>>>(p_qkv, p_owb, o_b, q, out);
}

// round 16
// speedup vs baseline: 1.0126x; 1.0126x over previous
#include <cuda_runtime.h>
#include <cuda_bf16.h>
#include <cstdint>
#include <cstddef>

// Problem constants
#define HWC   65536          // H*W = 256*256
#define CCH   256            // channels
#define NBAT  4
#define NHEAD 8
#define HD    32
#define NGRP  32
#define CPG   8              // channels per group

// ===========================================================================
// Helpers
// ===========================================================================
__device__ __forceinline__ uint32_t smem_u32(const void* p) {
    uint32_t a;
    asm("{ .reg .u64 t; cvta.to.shared.u64 t, %1; cvt.u32.u64 %0, t; }"
        : "=r"(a) : "l"(p));
    return a;
}
__device__ __forceinline__ void ldsm_x4(uint32_t* r, uint32_t addr) {
    asm volatile("ldmatrix.sync.aligned.m8n8.x4.shared.b16 {%0,%1,%2,%3}, [%4];"
        : "=r"(r[0]), "=r"(r[1]), "=r"(r[2]), "=r"(r[3]) : "r"(addr));
}
__device__ __forceinline__ void ldsm_x4t(uint32_t* r, uint32_t addr) {
    asm volatile("ldmatrix.sync.aligned.m8n8.x4.trans.shared.b16 {%0,%1,%2,%3}, [%4];"
        : "=r"(r[0]), "=r"(r[1]), "=r"(r[2]), "=r"(r[3]) : "r"(addr));
}
__device__ __forceinline__ void mma_bf16(float* c, const uint32_t* a, const uint32_t* b) {
    asm volatile("mma.sync.aligned.m16n8k16.row.col.f32.bf16.bf16.f32 "
        "{%0,%1,%2,%3}, {%4,%5,%6,%7}, {%8,%9}, {%0,%1,%2,%3};"
        : "+f"(c[0]), "+f"(c[1]), "+f"(c[2]), "+f"(c[3])
        : "r"(a[0]), "r"(a[1]), "r"(a[2]), "r"(a[3]), "r"(b[0]), "r"(b[1]));
}
__device__ __forceinline__ void cp16(uint32_t dst, const void* src) {
    asm volatile("cp.async.cg.shared.global [%0], [%1], 16;" :: "r"(dst), "l"(src));
}
#define CP_COMMIT() asm volatile("cp.async.commit_group;" ::: "memory")
#define CP_WAIT0()  asm volatile("cp.async.wait_group 0;" ::: "memory")
#define CP_WAIT1()  asm volatile("cp.async.wait_group 1;" ::: "memory")

__device__ __forceinline__ void store2(float* p, float x, float y) {
    *(float2*)p = make_float2(x, y);
}
__device__ __forceinline__ void store2(__nv_bfloat16* p, float x, float y) {
    *(__nv_bfloat162*)p = __floats2bfloat162_rn(x, y);
}
__device__ __forceinline__ uint32_t pack_bf2(float x, float y) {
    __nv_bfloat162 h = __floats2bfloat162_rn(x, y);
    return *reinterpret_cast<uint32_t*>(&h);
}
// spatial index n (= h*256+w) -> window-tiled index win*64 + tok
__device__ __forceinline__ int remap_win(int n) {
    return (((n >> 11) * 32 + ((n >> 3) & 31)) << 6) + (((n >> 8) & 7) << 3) + (n & 7);
}

// ---------------------------------------------------------------------------
// Scratch
// ---------------------------------------------------------------------------
__device__ float g_psum[NBAT * NGRP * 4 * 2];
__device__ __align__(16) __nv_bfloat16 g_wadjb[NBAT * 768 * 256];  // GN-folded QKV weights
__device__ __align__(16) __nv_bfloat16 g_owb[256 * 256];           // o_w bf16 [o][c]
__device__ float g_badj[NBAT * 768];
__device__ __align__(16) __nv_bfloat16 g_qbf[(size_t)NBAT * CCH * HWC];  // q bf16, WINDOW-TILED n
__device__ __align__(16) __nv_bfloat16 g_qkv[(size_t)NBAT * 768 * HWC];  // [b][768][win*64+tok]

// ---------------------------------------------------------------------------
// K1: GroupNorm partial sums + q -> bf16 (window-tiled layout).
// The scatter (8B stores at 128B-ish stride) lives here, where there's slack.
// ---------------------------------------------------------------------------
__global__ __launch_bounds__(256) void gn_part_kernel(const float* __restrict__ q,
                                                      __nv_bfloat16* __restrict__ qbf)
{
    const int bx = blockIdx.x;
    const int bg = bx >> 2, slice = bx & 3;
    const size_t off4 = (size_t)bg * (CPG * HWC / 4) + (size_t)slice * (CPG * HWC / 16);
    const float4* base = (const float4*)q + off4;
    float s = 0.f, s2 = 0.f;
#pragma unroll 4
    for (int i = threadIdx.x; i < CPG * HWC / 16; i += 256) {
        float4 v = base[i];
        s  += v.x + v.y + v.z + v.w;
        s2 += v.x*v.x + v.y*v.y + v.z*v.z + v.w*v.w;
        // global element index -> (channel, spatial n); write window-tiled
        const size_t fe = (off4 + i) * 4;
        const int ch = (int)(fe >> 16);            // global channel incl. batch
        const int n  = (int)(fe & (HWC - 1));
        uint2 u;
        u.x = pack_bf2(v.x, v.y);
        u.y = pack_bf2(v.z, v.w);
        *(uint2*)(qbf + ((size_t)ch << 16) + remap_win(n)) = u;
    }
    __shared__ float rs[256], rs2[256];
    rs[threadIdx.x] = s; rs2[threadIdx.x] = s2;
    __syncthreads();
    for (int off = 128; off > 0; off >>= 1) {
        if (threadIdx.x < off) {
            rs [threadIdx.x] += rs [threadIdx.x + off];
            rs2[threadIdx.x] += rs2[threadIdx.x + off];
        }
        __syncthreads();
    }
    if (threadIdx.x == 0) {
        g_psum[bx * 2 + 0] = rs[0];
        g_psum[bx * 2 + 1] = rs2[0];
    }
}

// ---------------------------------------------------------------------------
// K2: finalize stats + fold GroupNorm into QKV weights (32^-0.5 into k)
// ---------------------------------------------------------------------------
__global__ __launch_bounds__(256) void prep_weights_kernel(
    const float* __restrict__ q_w, const float* __restrict__ q_b,
    const float* __restrict__ k_w, const float* __restrict__ k_b,
    const float* __restrict__ v_w, const float* __restrict__ v_b,
    const float* __restrict__ gn_w, const float* __restrict__ gn_b)
{
    int m = blockIdx.x;
    int b = blockIdx.y;
    int t = m >> 8, o = m & 255;
    const float* W; const float* Bv;
    if      (t == 0) { W = q_w; Bv = q_b; }
    else if (t == 1) { W = k_w; Bv = k_b; }
    else             { W = v_w; Bv = v_b; }
    const float KS = (t == 1) ? 0.17677669529663687f : 1.0f;

    int c = threadIdx.x;
    int g = c >> 3;
    const int bg = b * NGRP + g;
    float s  = g_psum[bg * 8 + 0] + g_psum[bg * 8 + 2] + g_psum[bg * 8 + 4] + g_psum[bg * 8 + 6];
    float s2 = g_psum[bg * 8 + 1] + g_psum[bg * 8 + 3] + g_psum[bg * 8 + 5] + g_psum[bg * 8 + 7];
    const float invN = 1.f / (float)(CPG * HWC);
    float mean = s * invN;
    float var  = s2 * invN - mean * mean;
    float rstd = rsqrtf(var + 1e-6f);

    float sc = rstd * gn_w[c];
    float sh = gn_b[c] - mean * sc;
    float wv = W[o * 256 + c];

    g_wadjb[((size_t)b * 768 + m) * 256 + c] = __float2bfloat16(wv * sc * KS);

    __shared__ float red[256];
    red[c] = wv * sh;
    __syncthreads();
    for (int off = 128; off > 0; off >>= 1) {
        if (c < off) red[c] += red[c + off];
        __syncthreads();
    }
    if (c == 0) g_badj[(size_t)b * 768 + m] = (Bv[o] + red[0]) * KS;
}

__global__ __launch_bounds__(256) void prep_ow_kernel(const float* __restrict__ ow)
{
    int o = blockIdx.x, c = threadIdx.x;
    g_owb[o * 256 + c] = __float2bfloat16(ow[o * 256 + c]);
}

// ---------------------------------------------------------------------------
// K3: QKV bf16 mma.sync GEMM (validated R13 pipeline). X is window-tiled, so
// loads AND stores are fully contiguous; n is the window-tiled index.
// ---------------------------------------------------------------------------
#define SM_X    0
#define SM_A    65536
#define SM_TOT  114688

__device__ __forceinline__ void stage_x(uint32_t sb, const __nv_bfloat16* Xb, int tid)
{
#pragma unroll 4
    for (int i = tid; i < 4096; i += 256) {
        int k = i >> 4, g = i & 15;
        cp16(sb + SM_X + k * 256 + ((g ^ (k & 7)) << 4),
             Xb + (size_t)k * HWC + g * 8);
    }
}
__device__ __forceinline__ void stage_aq(uint32_t sb, const __nv_bfloat16* Asrc,
                                         uint32_t buf, int tid)
{
#pragma unroll
    for (int i = tid; i < 1024; i += 256) {
        int m = i >> 3, ch = i & 7;
        cp16(sb + SM_A + buf * 16384 + m * 128 + ((ch ^ (m & 7)) << 4),
             Asrc + (size_t)m * 256 + ch * 8);
    }
}

__global__ __launch_bounds__(256, 2) void gemm_qkv_kernel(
    const __nv_bfloat16* __restrict__ Abf,
    const float* __restrict__ bias,
    const __nv_bfloat16* __restrict__ X,
    __nv_bfloat16* __restrict__ out)
{
    extern __shared__ char smem[];
    const uint32_t sb = smem_u32(smem);
    const int tid = threadIdx.x, wid = tid >> 5, lane = tid & 31;
    const int b = blockIdx.y;
    const int n0 = blockIdx.x * 128;
    const int MT = 6;

    const __nv_bfloat16* Ab = Abf + (size_t)b * 768 * 256;

    stage_x(sb, X + (size_t)b * CCH * HWC + n0, tid);
    stage_aq(sb, Ab, 0, tid);
    CP_COMMIT();
    stage_aq(sb, Ab + 64, 1, tid);
    CP_COMMIT();

    const int wm = (wid & 3) * 32;
    const int wn = (wid >> 2) * 64;
    const int arow = wm + (lane & 15);
    const int asel = lane >> 4;
    const int ar7  = arow & 7;
    const int gg = lane >> 3, ll = lane & 7;
    const int kbl = (gg & 1) * 8 + ll;
    const int br7 = kbl & 7;
    uint32_t bBase[4];
#pragma unroll
    for (int j = 0; j < 4; j++) {
        int cn = (wn >> 3) + j * 2 + (gg >> 1);
        bBase[j] = sb + SM_X + (uint32_t)kbl * 256 + (uint32_t)((cn ^ br7) << 4);
    }
    const int er = lane >> 2, ec = (lane & 3) * 2;

    int cur = 0;
    for (int mt = 0; mt < MT; mt++) {
        float c[2][8][4];
#pragma unroll
        for (int mi = 0; mi < 2; mi++)
#pragma unroll
            for (int ni = 0; ni < 8; ni++)
#pragma unroll
                for (int t = 0; t < 4; t++) c[mi][ni][t] = 0.f;

#pragma unroll
        for (int q = 0; q < 4; q++) {
            const int qi = mt * 4 + q;
            CP_WAIT1();
            __syncthreads();
            const int nqi = qi + 2;
            if (nqi < MT * 4) {
                const int nbuf = (cur == 0) ? 2 : cur - 1;
                stage_aq(sb, Ab + (size_t)(nqi >> 2) * 32768 + (nqi & 3) * 64,
                         (uint32_t)nbuf, tid);
            }
            CP_COMMIT();
            const uint32_t abuf = sb + SM_A + (uint32_t)cur * 16384;

#pragma unroll
            for (int ksl = 0; ksl < 4; ksl++) {
                uint32_t a0[4], a1[4];
                const uint32_t aoff = (uint32_t)(((ksl * 2 + asel) ^ ar7) << 4);
                ldsm_x4(a0, abuf + (uint32_t)arow * 128 + aoff);
                ldsm_x4(a1, abuf + (uint32_t)(arow + 16) * 128 + aoff);
                const uint32_t xoff = (uint32_t)(q * 16384 + ksl * 4096);
                uint32_t bf[8][2];
#pragma unroll
                for (int j = 0; j < 4; j++) {
                    uint32_t r[4];
                    ldsm_x4t(r, bBase[j] + xoff);
                    bf[2 * j][0] = r[0];     bf[2 * j][1] = r[1];
                    bf[2 * j + 1][0] = r[2]; bf[2 * j + 1][1] = r[3];
                }
#pragma unroll
                for (int ni = 0; ni < 8; ni++) {
                    mma_bf16(c[0][ni], a0, bf[ni]);
                    mma_bf16(c[1][ni], a1, bf[ni]);
                }
            }
            cur = (cur == 2) ? 0 : cur + 1;
        }

        // epilogue: bias + contiguous window-tiled store (bf16)
#pragma unroll
        for (int mi = 0; mi < 2; mi++) {
            const int m0g = mt * 128 + wm + mi * 16 + er;
            const float bv0 = bias[(size_t)b * 768 + m0g];
            const float bv1 = bias[(size_t)b * 768 + m0g + 8];
            __nv_bfloat16* ob = out + ((size_t)b * 768 + m0g) * HWC + n0 + wn + ec;
#pragma unroll
            for (int ni = 0; ni < 8; ni++) {
                store2(ob + ni * 8,           c[mi][ni][0] + bv0, c[mi][ni][1] + bv0);
                store2(ob + 8 * HWC + ni * 8, c[mi][ni][2] + bv1, c[mi][ni][3] + bv1);
            }
        }
    }
}

// ---------------------------------------------------------------------------
// K4: fused windowed MHA + output projection + residual (validated R15).
// One block per (window, batch): 512 threads = 16 warps.
// ---------------------------------------------------------------------------
#define SMF_AT  98304
#define SMF_OW  131072
#define SMF_TOT 196608

__device__ __forceinline__ void stage_ow(uint32_t sb, const __nv_bfloat16* owb,
                                         int kc, uint32_t buf, int tid)
{
    const __nv_bfloat16* src = owb + kc * 64;
#pragma unroll
    for (int i = tid; i < 2048; i += 512) {
        int oc = i >> 3, ch = i & 7;
        cp16(sb + SMF_OW + buf * 32768 + oc * 128 + ((ch ^ (oc & 7)) << 4),
             src + (size_t)oc * 256 + ch * 8);
    }
}

__global__ __launch_bounds__(512) void attn_oproj_kernel(
    const __nv_bfloat16* __restrict__ qkv,
    const __nv_bfloat16* __restrict__ owb,
    const float* __restrict__ o_b,
    const float* __restrict__ qres,
    float* __restrict__ out)
{
    extern __shared__ char smem[];
    const uint32_t sb = smem_u32(smem);
    const int tid = threadIdx.x, wid = tid >> 5, lane = tid & 31;
    const int win = blockIdx.x, b = blockIdx.y;
    const int wy = win >> 5, wx = win & 31;
    const int h0 = wy * 8, w0 = wx * 8;

    // stage Q/K/V for all 8 heads FIRST (sync-critical), then o_w prefetch
    {
        const __nv_bfloat16* src = qkv + (size_t)b * 768 * HWC + (size_t)win * 64;
#pragma unroll
        for (int idx = tid; idx < 6144; idx += 512) {
            int chk = idx & 7, d = (idx >> 3) & 31, head = (idx >> 8) & 7, t = idx >> 11;
            int ch = t * 256 + head * 32 + d;
            uint4 v = *(const uint4*)(src + (size_t)ch * HWC + chk * 8);
            *(uint4*)(smem + head * 12288 + t * 4096 + d * 128 + ((chk ^ (d & 7)) << 4)) = v;
        }
    }
    stage_ow(sb, owb, 0, 0, tid); CP_COMMIT();
    stage_ow(sb, owb, 1, 1, tid); CP_COMMIT();
    __syncthreads();

    // ================= Phase A: attention =================
    const uint32_t Qs = sb + (wid >> 1) * 12288;
    const uint32_t Ks = Qs + 4096;
    const uint32_t Vs = Qs + 8192;
    const int mbase = (wid & 1) * 32;
    const int rlo = lane & 7, rsel = lane >> 4, csel = (lane >> 3) & 1;
    const int gg = lane >> 3, ll = lane & 7;

    {
        uint32_t qa[2][2][4];
#pragma unroll
        for (int mi = 0; mi < 2; mi++)
#pragma unroll
            for (int ks = 0; ks < 2; ks++) {
                int rd = ks * 16 + rsel * 8 + rlo;
                int chunk = (mbase >> 3) + mi * 2 + csel;
                ldsm_x4t(qa[mi][ks], Qs + rd * 128 + ((chunk ^ (rd & 7)) << 4));
            }

        float c[2][8][4];
#pragma unroll
        for (int mi = 0; mi < 2; mi++)
#pragma unroll
            for (int ni = 0; ni < 8; ni++)
#pragma unroll
                for (int t = 0; t < 4; t++) c[mi][ni][t] = 0.f;

#pragma unroll
        for (int ks = 0; ks < 2; ks++) {
            int rd = ks * 16 + rsel * 8 + rlo;
#pragma unroll
            for (int ng = 0; ng < 4; ng++) {
                int chunk = ng * 2 + csel;
                uint32_t r[4];
                ldsm_x4t(r, Ks + rd * 128 + ((chunk ^ (rd & 7)) << 4));
                uint32_t b0[2] = {r[0], r[2]}, b1[2] = {r[1], r[3]};
                mma_bf16(c[0][ng * 2],     qa[0][ks], b0);
                mma_bf16(c[0][ng * 2 + 1], qa[0][ks], b1);
                mma_bf16(c[1][ng * 2],     qa[1][ks], b0);
                mma_bf16(c[1][ng * 2 + 1], qa[1][ks], b1);
            }
        }

        float rs[2][2] = {{0.f, 0.f}, {0.f, 0.f}};
        uint32_t pa[2][4][4];
#pragma unroll
        for (int mi = 0; mi < 2; mi++)
#pragma unroll
            for (int ni = 0; ni < 8; ni++) {
                float e0 = __expf(c[mi][ni][0]);
                float e1 = __expf(c[mi][ni][1]);
                float e2 = __expf(c[mi][ni][2]);
                float e3 = __expf(c[mi][ni][3]);
                rs[mi][0] += e0 + e1;
                rs[mi][1] += e2 + e3;
                int ks = ni >> 1, half = ni & 1;
                pa[mi][ks][half * 2]     = pack_bf2(e0, e1);
                pa[mi][ks][half * 2 + 1] = pack_bf2(e2, e3);
            }
#pragma unroll
        for (int mi = 0; mi < 2; mi++)
#pragma unroll
            for (int j = 0; j < 2; j++) {
                rs[mi][j] += __shfl_xor_sync(0xffffffff, rs[mi][j], 1);
                rs[mi][j] += __shfl_xor_sync(0xffffffff, rs[mi][j], 2);
            }

        float o[2][4][4];
#pragma unroll
        for (int mi = 0; mi < 2; mi++)
#pragma unroll
            for (int nj = 0; nj < 4; nj++)
#pragma unroll
                for (int t = 0; t < 4; t++) o[mi][nj][t] = 0.f;

#pragma unroll
        for (int ks = 0; ks < 4; ks++) {
#pragma unroll
            for (int njg = 0; njg < 2; njg++) {
                int rd = njg * 16 + rsel * 8 + rlo;
                int chunk = ks * 2 + csel;
                uint32_t r[4];
                ldsm_x4(r, Vs + rd * 128 + ((chunk ^ (rd & 7)) << 4));
                uint32_t b0[2] = {r[0], r[1]}, b1[2] = {r[2], r[3]};
                mma_bf16(o[0][njg * 2],     pa[0][ks], b0);
                mma_bf16(o[0][njg * 2 + 1], pa[0][ks], b1);
                mma_bf16(o[1][njg * 2],     pa[1][ks], b0);
                mma_bf16(o[1][njg * 2 + 1], pa[1][ks], b1);
            }
        }

        // store normalized bf16 to attnout[c][tok] with B-operand swizzle
        const int headc = (wid >> 1) * 32;
#pragma unroll
        for (int mi = 0; mi < 2; mi++) {
            const float inv0 = 1.f / rs[mi][0];
            const float inv1 = 1.f / rs[mi][1];
            const int t0 = mbase + mi * 16 + (lane >> 2);
            const int t1 = t0 + 8;
#pragma unroll
            for (int nj = 0; nj < 4; nj++) {
                const int d0 = headc + nj * 8 + (lane & 3) * 2;
                const int d1 = d0 + 1;
                *(__nv_bfloat16*)(smem + SMF_AT + d0 * 128 + (((t0 >> 3) ^ (d0 & 7)) << 4) + (t0 & 7) * 2)
                    = __float2bfloat16(o[mi][nj][0] * inv0);
                *(__nv_bfloat16*)(smem + SMF_AT + d1 * 128 + (((t0 >> 3) ^ (d1 & 7)) << 4) + (t0 & 7) * 2)
                    = __float2bfloat16(o[mi][nj][1] * inv0);
                *(__nv_bfloat16*)(smem + SMF_AT + d0 * 128 + (((t1 >> 3) ^ (d0 & 7)) << 4) + (t1 & 7) * 2)
                    = __float2bfloat16(o[mi][nj][2] * inv1);
                *(__nv_bfloat16*)(smem + SMF_AT + d1 * 128 + (((t1 >> 3) ^ (d1 & 7)) << 4) + (t1 & 7) * 2)
                    = __float2bfloat16(o[mi][nj][3] * inv1);
            }
        }
    }
    __syncthreads();
    CP_WAIT0();
    __syncthreads();

    // ================= Phase B: O-projection =================
    const int arow = wid * 16 + (lane & 15);
    const int asel = lane >> 4;
    const int ar7  = arow & 7;
    const int kbl = (gg & 1) * 8 + ll;
    uint32_t bBase[4];
#pragma unroll
    for (int j = 0; j < 4; j++) {
        int cn = j * 2 + (gg >> 1);
        bBase[j] = sb + SMF_AT + (uint32_t)kbl * 128 + (uint32_t)((cn ^ (kbl & 7)) << 4);
    }

    float co[8][4];
#pragma unroll
    for (int ni = 0; ni < 8; ni++)
#pragma unroll
        for (int t = 0; t < 4; t++) co[ni][t] = 0.f;

#define OPROJ_CHUNK(KC, BUF) do {                                              \
    const uint32_t abufq = sb + SMF_OW + (uint32_t)(BUF) * 32768;              \
    _Pragma("unroll")                                                          \
    for (int ksl = 0; ksl < 4; ksl++) {                                        \
        uint32_t a[4];                                                         \
        ldsm_x4(a, abufq + (uint32_t)arow * 128                                \
                   + (uint32_t)(((ksl * 2 + asel) ^ ar7) << 4));               \
        const uint32_t xoff = (uint32_t)((KC) * 8192 + ksl * 2048);            \
        uint32_t bf[8][2];                                                     \
        _Pragma("unroll")                                                      \
        for (int j = 0; j < 4; j++) {                                          \
            uint32_t r[4];                                                     \
            ldsm_x4t(r, bBase[j] + xoff);                                      \
            bf[2 * j][0] = r[0];     bf[2 * j][1] = r[1];                      \
            bf[2 * j + 1][0] = r[2]; bf[2 * j + 1][1] = r[3];                  \
        }                                                                      \
        _Pragma("unroll")                                                      \
        for (int ni = 0; ni < 8; ni++) mma_bf16(co[ni], a, bf[ni]);            \
    }                                                                          \
} while (0)

    OPROJ_CHUNK(0, 0);
    __syncthreads();
    stage_ow(sb, owb, 2, 0, tid); CP_COMMIT();
    OPROJ_CHUNK(1, 1);
    __syncthreads();
    stage_ow(sb, owb, 3, 1, tid); CP_COMMIT();
    CP_WAIT1();
    __syncthreads();
    OPROJ_CHUNK(2, 0);
    CP_WAIT0();
    __syncthreads();
    OPROJ_CHUNK(3, 1);

    // epilogue: bias + fp32 residual + 2^-0.5, spatial layout (32B segments)
    {
        const int er = lane >> 2, ec = (lane & 3) * 2;
        const int oc0 = wid * 16 + er;
        const float bv0 = o_b[oc0], bv1 = o_b[oc0 + 8];
        const size_t base0 = ((size_t)b * 256 + oc0) * HWC;
        const float sc = 0.70710678118654752f;
#pragma unroll
        for (int ni = 0; ni < 8; ni++) {
            const int pos = (h0 + ni) * 256 + w0 + ec;
            float2 r0 = *(const float2*)(qres + base0 + pos);
            float2 r1 = *(const float2*)(qres + base0 + 8 * HWC + pos);
            store2(out + base0 + pos,
                   (co[ni][0] + bv0 + r0.x) * sc, (co[ni][1] + bv0 + r0.y) * sc);
            store2(out + base0 + 8 * HWC + pos,
                   (co[ni][2] + bv1 + r1.x) * sc, (co[ni][3] + bv1 + r1.y) * sc);
        }
    }
#undef OPROJ_CHUNK
}

// ---------------------------------------------------------------------------
// Launch
// ---------------------------------------------------------------------------
extern "C" void kernel_launch(void* const* d_in, const int* in_sizes, int n_in,
                              void* d_out, int out_size)
{
    const float* q    = (const float*)d_in[0];
    const float* gn_w = (const float*)d_in[1];
    const float* gn_b = (const float*)d_in[2];
    const float* q_w  = (const float*)d_in[3];
    const float* q_b  = (const float*)d_in[4];
    const float* k_w  = (const float*)d_in[5];
    const float* k_b  = (const float*)d_in[6];
    const float* v_w  = (const float*)d_in[7];
    const float* v_b  = (const float*)d_in[8];
    const float* o_w  = (const float*)d_in[9];
    const float* o_b  = (const float*)d_in[10];
    float* out = (float*)d_out;

    __nv_bfloat16 *p_wadjb, *p_owb, *p_qbf, *p_qkv;
    float *p_badj;
    cudaGetSymbolAddress((void**)&p_wadjb, g_wadjb);
    cudaGetSymbolAddress((void**)&p_owb,   g_owb);
    cudaGetSymbolAddress((void**)&p_badj,  g_badj);
    cudaGetSymbolAddress((void**)&p_qbf,   g_qbf);
    cudaGetSymbolAddress((void**)&p_qkv,   g_qkv);

    cudaFuncSetAttribute((const void*)gemm_qkv_kernel,
                         cudaFuncAttributeMaxDynamicSharedMemorySize, SM_TOT);
    cudaFuncSetAttribute((const void*)attn_oproj_kernel,
                         cudaFuncAttributeMaxDynamicSharedMemorySize, SMF_TOT);

    // 1. GroupNorm partial stats + q -> bf16 (window-tiled)
    gn_part_kernel<<<NBAT * NGRP * 4, 256>>>(q, p_qbf);

    // 2. Finalize stats + fold GN into QKV weights; o_w -> bf16
    prep_weights_kernel<<<dim3(768, NBAT), 256>>>(q_w, q_b, k_w, k_b, v_w, v_b, gn_w, gn_b);
    prep_ow_kernel<<<256, 256>>>(o_w);

    // 3. Fused (GN + QKV projection), window-tiled everywhere
    gemm_qkv_kernel<<<dim3(512, NBAT), 256, SM_TOT>>>(p_wadjb, p_badj, p_qbf, p_qkv);

    // 4. Fused attention + O-proj + residual
    attn_oproj_kernel<<<dim3(1024, NBAT), 512, SMF_TOT>>>(p_qkv, p_owb, o_b, q, out);
}

// round 17
// speedup vs baseline: 1.0842x; 1.0707x over previous
#include <cuda_runtime.h>
#include <cuda_bf16.h>
#include <cstdint>
#include <cstddef>

// Problem constants
#define HWC   65536          // H*W = 256*256
#define CCH   256            // channels
#define NBAT  4
#define NHEAD 8
#define HD    32
#define NGRP  32
#define CPG   8              // channels per group

// ===========================================================================
// Helpers
// ===========================================================================
__device__ __forceinline__ uint32_t smem_u32(const void* p) {
    uint32_t a;
    asm("{ .reg .u64 t; cvta.to.shared.u64 t, %1; cvt.u32.u64 %0, t; }"
        : "=r"(a) : "l"(p));
    return a;
}
__device__ __forceinline__ void ldsm_x4(uint32_t* r, uint32_t addr) {
    asm volatile("ldmatrix.sync.aligned.m8n8.x4.shared.b16 {%0,%1,%2,%3}, [%4];"
        : "=r"(r[0]), "=r"(r[1]), "=r"(r[2]), "=r"(r[3]) : "r"(addr));
}
__device__ __forceinline__ void ldsm_x4t(uint32_t* r, uint32_t addr) {
    asm volatile("ldmatrix.sync.aligned.m8n8.x4.trans.shared.b16 {%0,%1,%2,%3}, [%4];"
        : "=r"(r[0]), "=r"(r[1]), "=r"(r[2]), "=r"(r[3]) : "r"(addr));
}
__device__ __forceinline__ void mma_bf16(float* c, const uint32_t* a, const uint32_t* b) {
    asm volatile("mma.sync.aligned.m16n8k16.row.col.f32.bf16.bf16.f32 "
        "{%0,%1,%2,%3}, {%4,%5,%6,%7}, {%8,%9}, {%0,%1,%2,%3};"
        : "+f"(c[0]), "+f"(c[1]), "+f"(c[2]), "+f"(c[3])
        : "r"(a[0]), "r"(a[1]), "r"(a[2]), "r"(a[3]), "r"(b[0]), "r"(b[1]));
}
__device__ __forceinline__ void cp16(uint32_t dst, const void* src) {
    asm volatile("cp.async.cg.shared.global [%0], [%1], 16;" :: "r"(dst), "l"(src));
}
#define CP_COMMIT() asm volatile("cp.async.commit_group;" ::: "memory")
#define CP_WAIT0()  asm volatile("cp.async.wait_group 0;" ::: "memory")
#define CP_WAIT1()  asm volatile("cp.async.wait_group 1;" ::: "memory")

__device__ __forceinline__ void store2(float* p, float x, float y) {
    *(float2*)p = make_float2(x, y);
}
__device__ __forceinline__ void store2(__nv_bfloat16* p, float x, float y) {
    *(__nv_bfloat162*)p = __floats2bfloat162_rn(x, y);
}
__device__ __forceinline__ uint32_t pack_bf2(float x, float y) {
    __nv_bfloat162 h = __floats2bfloat162_rn(x, y);
    return *reinterpret_cast<uint32_t*>(&h);
}
// spatial index n (= h*256+w) -> window-tiled index win*64 + tok
__device__ __forceinline__ int remap_win(int n) {
    return (((n >> 11) * 32 + ((n >> 3) & 31)) << 6) + (((n >> 8) & 7) << 3) + (n & 7);
}

// ---------------------------------------------------------------------------
// Scratch
// ---------------------------------------------------------------------------
__device__ float g_psum[NBAT * NGRP * 4 * 2];
__device__ __align__(16) __nv_bfloat16 g_wadjb[NBAT * 768 * 256];  // GN-folded QKV weights
__device__ __align__(16) __nv_bfloat16 g_owb[256 * 256];           // o_w bf16 [o][c]
__device__ float g_badj[NBAT * 768];
__device__ __align__(16) __nv_bfloat16 g_qbf[(size_t)NBAT * CCH * HWC];  // q bf16, window-tiled n
__device__ __align__(16) __nv_bfloat16 g_qkv[(size_t)NBAT * 768 * HWC];  // [b][768][win*64+tok]

// ---------------------------------------------------------------------------
// K1: GroupNorm partial sums + q -> bf16 (window-tiled layout)
// ---------------------------------------------------------------------------
__global__ __launch_bounds__(256) void gn_part_kernel(const float* __restrict__ q,
                                                      __nv_bfloat16* __restrict__ qbf)
{
    const int bx = blockIdx.x;
    const int bg = bx >> 2, slice = bx & 3;
    const size_t off4 = (size_t)bg * (CPG * HWC / 4) + (size_t)slice * (CPG * HWC / 16);
    const float4* base = (const float4*)q + off4;
    float s = 0.f, s2 = 0.f;
#pragma unroll 4
    for (int i = threadIdx.x; i < CPG * HWC / 16; i += 256) {
        float4 v = base[i];
        s  += v.x + v.y + v.z + v.w;
        s2 += v.x*v.x + v.y*v.y + v.z*v.z + v.w*v.w;
        const size_t fe = (off4 + i) * 4;
        const int ch = (int)(fe >> 16);
        const int n  = (int)(fe & (HWC - 1));
        uint2 u;
        u.x = pack_bf2(v.x, v.y);
        u.y = pack_bf2(v.z, v.w);
        *(uint2*)(qbf + ((size_t)ch << 16) + remap_win(n)) = u;
    }
    __shared__ float rs[256], rs2[256];
    rs[threadIdx.x] = s; rs2[threadIdx.x] = s2;
    __syncthreads();
    for (int off = 128; off > 0; off >>= 1) {
        if (threadIdx.x < off) {
            rs [threadIdx.x] += rs [threadIdx.x + off];
            rs2[threadIdx.x] += rs2[threadIdx.x + off];
        }
        __syncthreads();
    }
    if (threadIdx.x == 0) {
        g_psum[bx * 2 + 0] = rs[0];
        g_psum[bx * 2 + 1] = rs2[0];
    }
}

// ---------------------------------------------------------------------------
// K2: finalize stats + fold GroupNorm into QKV weights (32^-0.5 into k)
// ---------------------------------------------------------------------------
__global__ __launch_bounds__(256) void prep_weights_kernel(
    const float* __restrict__ q_w, const float* __restrict__ q_b,
    const float* __restrict__ k_w, const float* __restrict__ k_b,
    const float* __restrict__ v_w, const float* __restrict__ v_b,
    const float* __restrict__ gn_w, const float* __restrict__ gn_b)
{
    int m = blockIdx.x;
    int b = blockIdx.y;
    int t = m >> 8, o = m & 255;
    const float* W; const float* Bv;
    if      (t == 0) { W = q_w; Bv = q_b; }
    else if (t == 1) { W = k_w; Bv = k_b; }
    else             { W = v_w; Bv = v_b; }
    const float KS = (t == 1) ? 0.17677669529663687f : 1.0f;

    int c = threadIdx.x;
    int g = c >> 3;
    const int bg = b * NGRP + g;
    float s  = g_psum[bg * 8 + 0] + g_psum[bg * 8 + 2] + g_psum[bg * 8 + 4] + g_psum[bg * 8 + 6];
    float s2 = g_psum[bg * 8 + 1] + g_psum[bg * 8 + 3] + g_psum[bg * 8 + 5] + g_psum[bg * 8 + 7];
    const float invN = 1.f / (float)(CPG * HWC);
    float mean = s * invN;
    float var  = s2 * invN - mean * mean;
    float rstd = rsqrtf(var + 1e-6f);

    float sc = rstd * gn_w[c];
    float sh = gn_b[c] - mean * sc;
    float wv = W[o * 256 + c];

    g_wadjb[((size_t)b * 768 + m) * 256 + c] = __float2bfloat16(wv * sc * KS);

    __shared__ float red[256];
    red[c] = wv * sh;
    __syncthreads();
    for (int off = 128; off > 0; off >>= 1) {
        if (c < off) red[c] += red[c + off];
        __syncthreads();
    }
    if (c == 0) g_badj[(size_t)b * 768 + m] = (Bv[o] + red[0]) * KS;
}

__global__ __launch_bounds__(256) void prep_ow_kernel(const float* __restrict__ ow)
{
    int o = blockIdx.x, c = threadIdx.x;
    g_owb[o * 256 + c] = __float2bfloat16(ow[o * 256 + c]);
}

// ---------------------------------------------------------------------------
// K3: QKV bf16 mma.sync GEMM (validated; window-tiled in and out)
// ---------------------------------------------------------------------------
#define SM_X    0
#define SM_A    65536
#define SM_TOT  114688

__device__ __forceinline__ void stage_x(uint32_t sb, const __nv_bfloat16* Xb, int tid)
{
#pragma unroll 4
    for (int i = tid; i < 4096; i += 256) {
        int k = i >> 4, g = i & 15;
        cp16(sb + SM_X + k * 256 + ((g ^ (k & 7)) << 4),
             Xb + (size_t)k * HWC + g * 8);
    }
}
__device__ __forceinline__ void stage_aq(uint32_t sb, const __nv_bfloat16* Asrc,
                                         uint32_t buf, int tid)
{
#pragma unroll
    for (int i = tid; i < 1024; i += 256) {
        int m = i >> 3, ch = i & 7;
        cp16(sb + SM_A + buf * 16384 + m * 128 + ((ch ^ (m & 7)) << 4),
             Asrc + (size_t)m * 256 + ch * 8);
    }
}

__global__ __launch_bounds__(256, 2) void gemm_qkv_kernel(
    const __nv_bfloat16* __restrict__ Abf,
    const float* __restrict__ bias,
    const __nv_bfloat16* __restrict__ X,
    __nv_bfloat16* __restrict__ out)
{
    extern __shared__ char smem[];
    const uint32_t sb = smem_u32(smem);
    const int tid = threadIdx.x, wid = tid >> 5, lane = tid & 31;
    const int b = blockIdx.y;
    const int n0 = blockIdx.x * 128;
    const int MT = 6;

    const __nv_bfloat16* Ab = Abf + (size_t)b * 768 * 256;

    stage_x(sb, X + (size_t)b * CCH * HWC + n0, tid);
    stage_aq(sb, Ab, 0, tid);
    CP_COMMIT();
    stage_aq(sb, Ab + 64, 1, tid);
    CP_COMMIT();

    const int wm = (wid & 3) * 32;
    const int wn = (wid >> 2) * 64;
    const int arow = wm + (lane & 15);
    const int asel = lane >> 4;
    const int ar7  = arow & 7;
    const int gg = lane >> 3, ll = lane & 7;
    const int kbl = (gg & 1) * 8 + ll;
    const int br7 = kbl & 7;
    uint32_t bBase[4];
#pragma unroll
    for (int j = 0; j < 4; j++) {
        int cn = (wn >> 3) + j * 2 + (gg >> 1);
        bBase[j] = sb + SM_X + (uint32_t)kbl * 256 + (uint32_t)((cn ^ br7) << 4);
    }
    const int er = lane >> 2, ec = (lane & 3) * 2;

    int cur = 0;
    for (int mt = 0; mt < MT; mt++) {
        float c[2][8][4];
#pragma unroll
        for (int mi = 0; mi < 2; mi++)
#pragma unroll
            for (int ni = 0; ni < 8; ni++)
#pragma unroll
                for (int t = 0; t < 4; t++) c[mi][ni][t] = 0.f;

#pragma unroll
        for (int q = 0; q < 4; q++) {
            const int qi = mt * 4 + q;
            CP_WAIT1();
            __syncthreads();
            const int nqi = qi + 2;
            if (nqi < MT * 4) {
                const int nbuf = (cur == 0) ? 2 : cur - 1;
                stage_aq(sb, Ab + (size_t)(nqi >> 2) * 32768 + (nqi & 3) * 64,
                         (uint32_t)nbuf, tid);
            }
            CP_COMMIT();
            const uint32_t abuf = sb + SM_A + (uint32_t)cur * 16384;

#pragma unroll
            for (int ksl = 0; ksl < 4; ksl++) {
                uint32_t a0[4], a1[4];
                const uint32_t aoff = (uint32_t)(((ksl * 2 + asel) ^ ar7) << 4);
                ldsm_x4(a0, abuf + (uint32_t)arow * 128 + aoff);
                ldsm_x4(a1, abuf + (uint32_t)(arow + 16) * 128 + aoff);
                const uint32_t xoff = (uint32_t)(q * 16384 + ksl * 4096);
                uint32_t bf[8][2];
#pragma unroll
                for (int j = 0; j < 4; j++) {
                    uint32_t r[4];
                    ldsm_x4t(r, bBase[j] + xoff);
                    bf[2 * j][0] = r[0];     bf[2 * j][1] = r[1];
                    bf[2 * j + 1][0] = r[2]; bf[2 * j + 1][1] = r[3];
                }
#pragma unroll
                for (int ni = 0; ni < 8; ni++) {
                    mma_bf16(c[0][ni], a0, bf[ni]);
                    mma_bf16(c[1][ni], a1, bf[ni]);
                }
            }
            cur = (cur == 2) ? 0 : cur + 1;
        }

#pragma unroll
        for (int mi = 0; mi < 2; mi++) {
            const int m0g = mt * 128 + wm + mi * 16 + er;
            const float bv0 = bias[(size_t)b * 768 + m0g];
            const float bv1 = bias[(size_t)b * 768 + m0g + 8];
            __nv_bfloat16* ob = out + ((size_t)b * 768 + m0g) * HWC + n0 + wn + ec;
#pragma unroll
            for (int ni = 0; ni < 8; ni++) {
                store2(ob + ni * 8,           c[mi][ni][0] + bv0, c[mi][ni][1] + bv0);
                store2(ob + 8 * HWC + ni * 8, c[mi][ni][2] + bv1, c[mi][ni][3] + bv1);
            }
        }
    }
}

// ---------------------------------------------------------------------------
// K4: fused windowed MHA + O-proj + residual, restructured for 2 CTAs/SM.
// Block = 256 threads, 88KB smem. Attention in 4 passes of 2 heads:
//   warp w -> head_local = w>>2, quarter = w&3 (16-row query quarter).
// attnout[c=256][tok=64] accumulated across passes (B-operand swizzle).
// O-proj: 8 warps x 32-oc tiles; o_w streamed through one 32KB buffer.
// ---------------------------------------------------------------------------
#define SMF_AT  24576
#define SMF_OW  57344
#define SMF_TOT 90112

__device__ __forceinline__ void stage_ow1(uint32_t sb, const __nv_bfloat16* owb,
                                          int kc, int tid)
{
    const __nv_bfloat16* src = owb + kc * 64;
#pragma unroll
    for (int i = tid; i < 2048; i += 256) {
        int oc = i >> 3, ch = i & 7;
        cp16(sb + SMF_OW + oc * 128 + ((ch ^ (oc & 7)) << 4),
             src + (size_t)oc * 256 + ch * 8);
    }
}

__global__ __launch_bounds__(256, 2) void attn_oproj_kernel(
    const __nv_bfloat16* __restrict__ qkv,
    const __nv_bfloat16* __restrict__ owb,
    const float* __restrict__ o_b,
    const float* __restrict__ qres,
    float* __restrict__ out)
{
    extern __shared__ char smem[];
    const uint32_t sb = smem_u32(smem);
    const int tid = threadIdx.x, wid = tid >> 5, lane = tid & 31;
    const int win = blockIdx.x, b = blockIdx.y;
    const int wy = win >> 5, wx = win & 31;
    const int h0 = wy * 8, w0 = wx * 8;

    // prefetch o_w chunk 0 (completes during attention)
    stage_ow1(sb, owb, 0, tid);
    CP_COMMIT();

    const __nv_bfloat16* src = qkv + (size_t)b * 768 * HWC + (size_t)win * 64;
    const int head_local = wid >> 2;        // 0..1
    const int quarter    = wid & 3;         // 0..3
    const int mbase = quarter * 16;
    const int rlo = lane & 7, rsel = lane >> 4, csel = (lane >> 3) & 1;
    const int gg = lane >> 3, ll = lane & 7;
    const uint32_t Qs = sb + head_local * 12288;
    const uint32_t Ks = Qs + 4096;
    const uint32_t Vs = Qs + 8192;

    // ================= Phase A: attention, 4 passes x 2 heads =================
#pragma unroll 1
    for (int p = 0; p < 4; p++) {
        if (p > 0) __syncthreads();             // prior pass LDSM done
        // stage 2 heads of Q/K/V
#pragma unroll
        for (int idx = tid; idx < 1536; idx += 256) {
            int chk = idx & 7, d = (idx >> 3) & 31, hl = (idx >> 8) & 1, t = idx >> 9;
            int ch = t * 256 + (p * 2 + hl) * 32 + d;
            uint4 v = *(const uint4*)(src + (size_t)ch * HWC + chk * 8);
            *(uint4*)(smem + hl * 12288 + t * 4096 + d * 128 + ((chk ^ (d & 7)) << 4)) = v;
        }
        __syncthreads();

        uint32_t qa[2][4];
#pragma unroll
        for (int ks = 0; ks < 2; ks++) {
            int rd = ks * 16 + rsel * 8 + rlo;
            int chunk = (mbase >> 3) + csel;
            ldsm_x4t(qa[ks], Qs + rd * 128 + ((chunk ^ (rd & 7)) << 4));
        }

        float c[8][4];
#pragma unroll
        for (int ni = 0; ni < 8; ni++)
#pragma unroll
            for (int t = 0; t < 4; t++) c[ni][t] = 0.f;

#pragma unroll
        for (int ks = 0; ks < 2; ks++) {
            int rd = ks * 16 + rsel * 8 + rlo;
#pragma unroll
            for (int ng = 0; ng < 4; ng++) {
                int chunk = ng * 2 + csel;
                uint32_t r[4];
                ldsm_x4t(r, Ks + rd * 128 + ((chunk ^ (rd & 7)) << 4));
                uint32_t b0[2] = {r[0], r[2]}, b1[2] = {r[1], r[3]};
                mma_bf16(c[ng * 2],     qa[ks], b0);
                mma_bf16(c[ng * 2 + 1], qa[ks], b1);
            }
        }

        float rs[2] = {0.f, 0.f};
        uint32_t pa[4][4];
#pragma unroll
        for (int ni = 0; ni < 8; ni++) {
            float e0 = __expf(c[ni][0]);
            float e1 = __expf(c[ni][1]);
            float e2 = __expf(c[ni][2]);
            float e3 = __expf(c[ni][3]);
            rs[0] += e0 + e1;
            rs[1] += e2 + e3;
            int ks = ni >> 1, half = ni & 1;
            pa[ks][half * 2]     = pack_bf2(e0, e1);
            pa[ks][half * 2 + 1] = pack_bf2(e2, e3);
        }
#pragma unroll
        for (int j = 0; j < 2; j++) {
            rs[j] += __shfl_xor_sync(0xffffffff, rs[j], 1);
            rs[j] += __shfl_xor_sync(0xffffffff, rs[j], 2);
        }

        float o[4][4];
#pragma unroll
        for (int nj = 0; nj < 4; nj++)
#pragma unroll
            for (int t = 0; t < 4; t++) o[nj][t] = 0.f;

#pragma unroll
        for (int ks = 0; ks < 4; ks++) {
#pragma unroll
            for (int njg = 0; njg < 2; njg++) {
                int rd = njg * 16 + rsel * 8 + rlo;
                int chunk = ks * 2 + csel;
                uint32_t r[4];
                ldsm_x4(r, Vs + rd * 128 + ((chunk ^ (rd & 7)) << 4));
                uint32_t b0[2] = {r[0], r[1]}, b1[2] = {r[2], r[3]};
                mma_bf16(o[njg * 2],     pa[ks], b0);
                mma_bf16(o[njg * 2 + 1], pa[ks], b1);
            }
        }

        // store normalized bf16 to attnout (B-operand swizzle)
        const int headc = (p * 2 + head_local) * 32;
        const float inv0 = 1.f / rs[0];
        const float inv1 = 1.f / rs[1];
        const int t0 = mbase + (lane >> 2);
        const int t1 = t0 + 8;
#pragma unroll
        for (int nj = 0; nj < 4; nj++) {
            const int d0 = headc + nj * 8 + (lane & 3) * 2;
            const int d1 = d0 + 1;
            *(__nv_bfloat16*)(smem + SMF_AT + d0 * 128 + (((t0 >> 3) ^ (d0 & 7)) << 4) + (t0 & 7) * 2)
                = __float2bfloat16(o[nj][0] * inv0);
            *(__nv_bfloat16*)(smem + SMF_AT + d1 * 128 + (((t0 >> 3) ^ (d1 & 7)) << 4) + (t0 & 7) * 2)
                = __float2bfloat16(o[nj][1] * inv0);
            *(__nv_bfloat16*)(smem + SMF_AT + d0 * 128 + (((t1 >> 3) ^ (d0 & 7)) << 4) + (t1 & 7) * 2)
                = __float2bfloat16(o[nj][2] * inv1);
            *(__nv_bfloat16*)(smem + SMF_AT + d1 * 128 + (((t1 >> 3) ^ (d1 & 7)) << 4) + (t1 & 7) * 2)
                = __float2bfloat16(o[nj][3] * inv1);
        }
    }
    __syncthreads();
    CP_WAIT0();          // o_w chunk 0 resident
    __syncthreads();

    // ================= Phase B: O-projection (8 warps x 32 oc) ===============
    const int arow = wid * 32 + (lane & 15);
    const int asel = lane >> 4;
    const int ar7  = arow & 7;
    const int kbl = (gg & 1) * 8 + ll;
    uint32_t bBase[4];
#pragma unroll
    for (int j = 0; j < 4; j++) {
        int cn = j * 2 + (gg >> 1);
        bBase[j] = sb + SMF_AT + (uint32_t)kbl * 128 + (uint32_t)((cn ^ (kbl & 7)) << 4);
    }

    float co[2][8][4];
#pragma unroll
    for (int mi = 0; mi < 2; mi++)
#pragma unroll
        for (int ni = 0; ni < 8; ni++)
#pragma unroll
            for (int t = 0; t < 4; t++) co[mi][ni][t] = 0.f;

#define OPROJ_CHUNK(KC) do {                                                   \
    _Pragma("unroll")                                                          \
    for (int ksl = 0; ksl < 4; ksl++) {                                        \
        uint32_t a0[4], a1[4];                                                 \
        const uint32_t aoff = (uint32_t)(((ksl * 2 + asel) ^ ar7) << 4);       \
        ldsm_x4(a0, sb + SMF_OW + (uint32_t)arow * 128 + aoff);                \
        ldsm_x4(a1, sb + SMF_OW + (uint32_t)(arow + 16) * 128 + aoff);         \
        const uint32_t xoff = (uint32_t)((KC) * 8192 + ksl * 2048);            \
        uint32_t bf[8][2];                                                     \
        _Pragma("unroll")                                                      \
        for (int j = 0; j < 4; j++) {                                          \
            uint32_t r[4];                                                     \
            ldsm_x4t(r, bBase[j] + xoff);                                      \
            bf[2 * j][0] = r[0];     bf[2 * j][1] = r[1];                      \
            bf[2 * j + 1][0] = r[2]; bf[2 * j + 1][1] = r[3];                  \
        }                                                                      \
        _Pragma("unroll")                                                      \
        for (int ni = 0; ni < 8; ni++) {                                       \
            mma_bf16(co[0][ni], a0, bf[ni]);                                   \
            mma_bf16(co[1][ni], a1, bf[ni]);                                   \
        }                                                                      \
    }                                                                          \
} while (0)

    OPROJ_CHUNK(0);
    __syncthreads();
    stage_ow1(sb, owb, 1, tid); CP_COMMIT(); CP_WAIT0();
    __syncthreads();
    OPROJ_CHUNK(1);
    __syncthreads();
    stage_ow1(sb, owb, 2, tid); CP_COMMIT(); CP_WAIT0();
    __syncthreads();
    OPROJ_CHUNK(2);
    __syncthreads();
    stage_ow1(sb, owb, 3, tid); CP_COMMIT(); CP_WAIT0();
    __syncthreads();
    OPROJ_CHUNK(3);

    // epilogue: bias + fp32 residual + 2^-0.5, spatial layout
    {
        const int er = lane >> 2, ec = (lane & 3) * 2;
        const float sc = 0.70710678118654752f;
#pragma unroll
        for (int mi = 0; mi < 2; mi++) {
            const int oc0 = wid * 32 + mi * 16 + er;
            const float bv0 = o_b[oc0], bv1 = o_b[oc0 + 8];
            const size_t base0 = ((size_t)b * 256 + oc0) * HWC;
#pragma unroll
            for (int ni = 0; ni < 8; ni++) {
                const int pos = (h0 + ni) * 256 + w0 + ec;
                float2 r0 = *(const float2*)(qres + base0 + pos);
                float2 r1 = *(const float2*)(qres + base0 + 8 * HWC + pos);
                store2(out + base0 + pos,
                       (co[mi][ni][0] + bv0 + r0.x) * sc, (co[mi][ni][1] + bv0 + r0.y) * sc);
                store2(out + base0 + 8 * HWC + pos,
                       (co[mi][ni][2] + bv1 + r1.x) * sc, (co[mi][ni][3] + bv1 + r1.y) * sc);
            }
        }
    }
#undef OPROJ_CHUNK
}

// ---------------------------------------------------------------------------
// Launch
// ---------------------------------------------------------------------------
extern "C" void kernel_launch(void* const* d_in, const int* in_sizes, int n_in,
                              void* d_out, int out_size)
{
    const float* q    = (const float*)d_in[0];
    const float* gn_w = (const float*)d_in[1];
    const float* gn_b = (const float*)d_in[2];
    const float* q_w  = (const float*)d_in[3];
    const float* q_b  = (const float*)d_in[4];
    const float* k_w  = (const float*)d_in[5];
    const float* k_b  = (const float*)d_in[6];
    const float* v_w  = (const float*)d_in[7];
    const float* v_b  = (const float*)d_in[8];
    const float* o_w  = (const float*)d_in[9];
    const float* o_b  = (const float*)d_in[10];
    float* out = (float*)d_out;

    __nv_bfloat16 *p_wadjb, *p_owb, *p_qbf, *p_qkv;
    float *p_badj;
    cudaGetSymbolAddress((void**)&p_wadjb, g_wadjb);
    cudaGetSymbolAddress((void**)&p_owb,   g_owb);
    cudaGetSymbolAddress((void**)&p_badj,  g_badj);
    cudaGetSymbolAddress((void**)&p_qbf,   g_qbf);
    cudaGetSymbolAddress((void**)&p_qkv,   g_qkv);

    cudaFuncSetAttribute((const void*)gemm_qkv_kernel,
                         cudaFuncAttributeMaxDynamicSharedMemorySize, SM_TOT);
    cudaFuncSetAttribute((const void*)attn_oproj_kernel,
                         cudaFuncAttributeMaxDynamicSharedMemorySize, SMF_TOT);

    // 1. GroupNorm partial stats + q -> bf16 (window-tiled)
    gn_part_kernel<<<NBAT * NGRP * 4, 256>>>(q, p_qbf);

    // 2. Finalize stats + fold GN into QKV weights; o_w -> bf16
    prep_weights_kernel<<<dim3(768, NBAT), 256>>>(q_w, q_b, k_w, k_b, v_w, v_b, gn_w, gn_b);
    prep_ow_kernel<<<256, 256>>>(o_w);

    // 3. Fused (GN + QKV projection), window-tiled everywhere
    gemm_qkv_kernel<<<dim3(512, NBAT), 256, SM_TOT>>>(p_wadjb, p_badj, p_qbf, p_qkv);

    // 4. Fused attention + O-proj + residual (2 CTAs/SM)
    attn_oproj_kernel<<<dim3(1024, NBAT), 256, SMF_TOT>>>(p_qkv, p_owb, o_b, q, out);
}